// round 2
// baseline (speedup 1.0000x reference)
#include <cuda_runtime.h>
#include <math.h>

#define D       512
#define G4      2048
#define R_REL   8
#define T_MAX   128
#define B_MAX   1024
#define NTOK_MAX 66048

// ---------------- device scratch (no allocations allowed) ----------------
__device__ float g_Wc[(size_t)R_REL * G4 * D];        // combined W_ih @ W_rel[r]  (33.5M f32)
__device__ float g_bc[R_REL * G4];                    // combined bias
__device__ float g_gatesx[(size_t)NTOK_MAX * G4];     // per-token input gates (541MB)
__device__ float g_hbuf[2][B_MAX * D];                // ping-pong hidden state
__device__ float g_cbuf[B_MAX * D];                   // cell state
__device__ int   g_cnt[R_REL];
__device__ int   g_off[R_REL];
__device__ int   g_cur[R_REL];
__device__ int   g_sorted[NTOK_MAX];
__device__ int   g_tokof[T_MAX * B_MAX];

// ---------------- init ----------------
__global__ void init_kernel() {
    int i = blockIdx.x * blockDim.x + threadIdx.x;
    if (i < 2 * B_MAX * D) ((float*)g_hbuf)[i] = 0.f;
    if (i < B_MAX * D)     g_cbuf[i] = 0.f;
    if (i < T_MAX * B_MAX) g_tokof[i] = -1;
    if (i < R_REL) { g_cnt[i] = 0; g_cur[i] = 0; }
}

// ---------------- bucket sort by relation ----------------
__global__ void hist_kernel(const int* __restrict__ rels, int n) {
    int i = blockIdx.x * blockDim.x + threadIdx.x;
    if (i < n) atomicAdd(&g_cnt[rels[i]], 1);
}
__global__ void scan_kernel() {
    int s = 0;
    for (int r = 0; r < R_REL; r++) { g_off[r] = s; g_cur[r] = s; s += g_cnt[r]; }
}
__global__ void scatter_kernel(const int* __restrict__ rels, int n) {
    int i = blockIdx.x * blockDim.x + threadIdx.x;
    if (i < n) {
        int pos = atomicAdd(&g_cur[rels[i]], 1);
        g_sorted[pos] = i;
    }
}
__global__ void tokscatter_kernel(const int* __restrict__ time_idx,
                                  const int* __restrict__ batch_idx, int n) {
    int i = blockIdx.x * blockDim.x + threadIdx.x;
    if (i < n) g_tokof[time_idx[i] * B_MAX + batch_idx[i]] = i;
}

// ---------------- Wc[r] = W_ih @ W_rel[r]  ([2048,512] = [2048,512]x[512,512]) ----------------
__global__ __launch_bounds__(256) void combine_wc(const float* __restrict__ Wih,
                                                  const float* __restrict__ Wrel) {
    int r = blockIdx.z;
    int j0 = blockIdx.y * 64, d0 = blockIdx.x * 64;
    __shared__ float As[16][64], Bs[16][64];
    int tid = threadIdx.x, tx = tid & 15, ty = tid >> 4;
    int am = tid >> 2, ak = (tid & 3) << 2;          // A (TN): row j0+am, k-contig
    int bk = tid >> 4, bd = (tid & 15) << 2;         // B (NN): row k0+bk, d-contig
    const float* B = Wrel + (size_t)r * D * D;
    float acc[4][4] = {};
    for (int k0 = 0; k0 < D; k0 += 16) {
        float4 av = *(const float4*)(Wih + (size_t)(j0 + am) * D + k0 + ak);
        As[ak + 0][am] = av.x; As[ak + 1][am] = av.y; As[ak + 2][am] = av.z; As[ak + 3][am] = av.w;
        *(float4*)&Bs[bk][bd] = *(const float4*)(B + (size_t)(k0 + bk) * D + d0 + bd);
        __syncthreads();
#pragma unroll
        for (int k = 0; k < 16; k++) {
            float4 a = *(const float4*)&As[k][ty << 2];
            float4 b = *(const float4*)&Bs[k][tx << 2];
            float aa[4] = {a.x, a.y, a.z, a.w}, bb[4] = {b.x, b.y, b.z, b.w};
#pragma unroll
            for (int i = 0; i < 4; i++)
#pragma unroll
                for (int j = 0; j < 4; j++) acc[i][j] += aa[i] * bb[j];
        }
        __syncthreads();
    }
#pragma unroll
    for (int i = 0; i < 4; i++)
#pragma unroll
        for (int j = 0; j < 4; j++)
            g_Wc[((size_t)r * G4 + j0 + (ty << 2) + i) * D + d0 + (tx << 2) + j] = acc[i][j];
}

// ---------------- bc[r][j] = W_ih[j,:]·b_rel[r] + b_ih[j] + b_hh[j] ----------------
__global__ void combine_bias(const float* __restrict__ Wih, const float* __restrict__ brel,
                             const float* __restrict__ bih, const float* __restrict__ bhh) {
    int r = blockIdx.y;
    int wid = threadIdx.x >> 5, lane = threadIdx.x & 31;
    int j = blockIdx.x * 8 + wid;
    float s = 0.f;
    for (int k = lane; k < D; k += 32) s += Wih[(size_t)j * D + k] * brel[r * D + k];
#pragma unroll
    for (int o = 16; o; o >>= 1) s += __shfl_xor_sync(0xffffffffu, s, o);
    if (lane == 0) g_bc[r * G4 + j] = s + bih[j] + bhh[j];
}

// ---------------- grouped x-projection: gates_x[tok] = embed[node]@Wc[rel]^T + bc[rel] ----------------
__global__ __launch_bounds__(256) void xproj_kernel(const float* __restrict__ embed,
                                                    const int* __restrict__ nodes) {
    // resolve flat row-tile -> (rel, tile-within-bucket)
    int ft = blockIdx.y;
    int rel = -1, tile = 0, cnt = 0, off = 0;
#pragma unroll
    for (int r = 0; r < R_REL; r++) {
        int c = g_cnt[r]; int tr = (c + 63) >> 6;
        if (rel < 0) {
            if (ft < tr) { rel = r; tile = ft; cnt = c; off = g_off[r]; }
            else ft -= tr;
        }
    }
    if (rel < 0) return;
    int j0 = blockIdx.x * 64;
    __shared__ float As[16][64], Bs[16][64];
    __shared__ int s_tok[64];
    __shared__ int s_node[64];
    int tid = threadIdx.x, tx = tid & 15, ty = tid >> 4;
    if (tid < 64) {
        int sp = tile * 64 + tid;
        int tok = -1, nd = 0;
        if (sp < cnt) { tok = g_sorted[off + sp]; nd = nodes[tok]; }
        s_tok[tid] = tok; s_node[tid] = nd;
    }
    __syncthreads();
    int am = tid >> 2, ak = (tid & 3) << 2;
    int nodeA = s_node[am];
    const float* Wc = g_Wc + (size_t)rel * G4 * D;
    float acc[4][4] = {};
    for (int k0 = 0; k0 < D; k0 += 16) {
        float4 av = *(const float4*)(embed + (size_t)nodeA * D + k0 + ak);
        As[ak + 0][am] = av.x; As[ak + 1][am] = av.y; As[ak + 2][am] = av.z; As[ak + 3][am] = av.w;
        float4 bv = *(const float4*)(Wc + (size_t)(j0 + am) * D + k0 + ak);
        Bs[ak + 0][am] = bv.x; Bs[ak + 1][am] = bv.y; Bs[ak + 2][am] = bv.z; Bs[ak + 3][am] = bv.w;
        __syncthreads();
#pragma unroll
        for (int k = 0; k < 16; k++) {
            float4 a = *(const float4*)&As[k][ty << 2];
            float4 b = *(const float4*)&Bs[k][tx << 2];
            float aa[4] = {a.x, a.y, a.z, a.w}, bb[4] = {b.x, b.y, b.z, b.w};
#pragma unroll
            for (int i = 0; i < 4; i++)
#pragma unroll
                for (int j = 0; j < 4; j++) acc[i][j] += aa[i] * bb[j];
        }
        __syncthreads();
    }
#pragma unroll
    for (int i = 0; i < 4; i++) {
        int row = (ty << 2) + i;
        int tok = s_tok[row];
        if (tok >= 0) {
#pragma unroll
            for (int j = 0; j < 4; j++) {
                int col = j0 + (tx << 2) + j;
                g_gatesx[(size_t)tok * G4 + col] = acc[i][j] + g_bc[rel * G4 + col];
            }
        }
    }
}

// ---------------- one LSTM time step: gates = gates_x + h@W_hh^T, then cell update ----------------
__global__ __launch_bounds__(256) void lstm_step(int t, const float* __restrict__ Whh,
                                                 const int* __restrict__ bsz,
                                                 float* __restrict__ out) {
    int bs = bsz[t];
    int row0 = blockIdx.y * 64;
    if (row0 >= bs) return;
    int d0 = blockIdx.x * 16;
    int cur = t & 1, nxt = cur ^ 1;
    __shared__ float As[16][64], Bs[16][64];
    __shared__ float gt[64][64];
    int tid = threadIdx.x, tx = tid & 15, ty = tid >> 4;
    int am = tid >> 2, ak = (tid & 3) << 2;
    // B row remap: block col jj in [0,64): gate = jj>>4, W_hh row = gate*512 + d0 + (jj&15)
    int whhrow = ((am >> 4) * D) + d0 + (am & 15);
    const float* hprev = g_hbuf[cur];
    float* hnext = g_hbuf[nxt];
    float acc[4][4] = {};
    for (int k0 = 0; k0 < D; k0 += 16) {
        float4 av = *(const float4*)(hprev + (size_t)(row0 + am) * D + k0 + ak);
        As[ak + 0][am] = av.x; As[ak + 1][am] = av.y; As[ak + 2][am] = av.z; As[ak + 3][am] = av.w;
        float4 bv = *(const float4*)(Whh + (size_t)whhrow * D + k0 + ak);
        Bs[ak + 0][am] = bv.x; Bs[ak + 1][am] = bv.y; Bs[ak + 2][am] = bv.z; Bs[ak + 3][am] = bv.w;
        __syncthreads();
#pragma unroll
        for (int k = 0; k < 16; k++) {
            float4 a = *(const float4*)&As[k][ty << 2];
            float4 b = *(const float4*)&Bs[k][tx << 2];
            float aa[4] = {a.x, a.y, a.z, a.w}, bb[4] = {b.x, b.y, b.z, b.w};
#pragma unroll
            for (int i = 0; i < 4; i++)
#pragma unroll
                for (int j = 0; j < 4; j++) acc[i][j] += aa[i] * bb[j];
        }
        __syncthreads();
    }
#pragma unroll
    for (int i = 0; i < 4; i++)
#pragma unroll
        for (int j = 0; j < 4; j++)
            gt[(ty << 2) + i][(tx << 2) + j] = acc[i][j];
    __syncthreads();
    // cell epilogue: 64 rows x 16 d = 1024 cells, 4 per thread
#pragma unroll
    for (int e = 0; e < 4; e++) {
        int cell = tid + e * 256;
        int row = cell >> 4, dl = cell & 15;
        int grow = row0 + row;
        if (grow < bs) {
            int gd = d0 + dl;
            int tok = g_tokof[t * B_MAX + grow];
            if (tok >= 0) {
                size_t gxb = (size_t)tok * G4 + gd;
                float gi = gt[row][dl]      + g_gatesx[gxb];
                float gf = gt[row][16 + dl] + g_gatesx[gxb + 512];
                float gg = gt[row][32 + dl] + g_gatesx[gxb + 1024];
                float go = gt[row][48 + dl] + g_gatesx[gxb + 1536];
                float co = g_cbuf[(size_t)grow * D + gd];
                float si = 1.f / (1.f + __expf(-gi));
                float sf = 1.f / (1.f + __expf(-gf));
                float so = 1.f / (1.f + __expf(-go));
                float cn = sf * co + si * tanhf(gg);
                float hv = so * tanhf(cn);
                g_cbuf[(size_t)grow * D + gd] = cn;
                hnext[(size_t)grow * D + gd] = hv;
                out[(size_t)tok * D + gd] = hv;
            } else {
                hnext[(size_t)grow * D + gd] = hprev[(size_t)grow * D + gd];
            }
        }
    }
}

// ---------------- launch ----------------
extern "C" void kernel_launch(void* const* d_in, const int* in_sizes, int n_in,
                              void* d_out, int out_size) {
    const float* embed     = (const float*)d_in[0];
    const float* Wrel      = (const float*)d_in[1];
    const float* brel      = (const float*)d_in[2];
    const float* Wih       = (const float*)d_in[3];
    const float* Whh       = (const float*)d_in[4];
    const float* bih       = (const float*)d_in[5];
    const float* bhh       = (const float*)d_in[6];
    const int*   nodes     = (const int*)d_in[7];
    const int*   rels      = (const int*)d_in[8];
    const int*   time_idx  = (const int*)d_in[9];
    const int*   batch_idx = (const int*)d_in[10];
    const int*   bsz       = (const int*)d_in[11];
    float* out = (float*)d_out;

    int ntok = in_sizes[7];
    int T    = in_sizes[11];
    if (ntok > NTOK_MAX) ntok = NTOK_MAX;
    if (T > T_MAX) T = T_MAX;

    init_kernel<<<(2 * B_MAX * D + 255) / 256, 256>>>();
    combine_wc<<<dim3(D / 64, G4 / 64, R_REL), 256>>>(Wih, Wrel);
    combine_bias<<<dim3(G4 / 8, R_REL), 256>>>(Wih, brel, bih, bhh);
    hist_kernel<<<(ntok + 255) / 256, 256>>>(rels, ntok);
    scan_kernel<<<1, 1>>>();
    scatter_kernel<<<(ntok + 255) / 256, 256>>>(rels, ntok);
    tokscatter_kernel<<<(ntok + 255) / 256, 256>>>(time_idx, batch_idx, ntok);
    xproj_kernel<<<dim3(G4 / 64, (ntok + 63) / 64 + R_REL), 256>>>(embed, nodes);
    for (int t = 0; t < T; t++)
        lstm_step<<<dim3(D / 16, B_MAX / 64), 256>>>(t, Whh, bsz, out);
}

// round 4
// speedup vs baseline: 1.6181x; 1.6181x over previous
#include <cuda_runtime.h>
#include <cuda_bf16.h>
#include <math.h>

#define D        512
#define G4       2048
#define R_REL    8
#define T_MAX    128
#define B_MAX    1024
#define NTOK_MAX 66048
#define NODES_MAX 50000

// ---------------- device scratch (no runtime allocation allowed) ----------------
__device__ float          g_Wc[(size_t)R_REL * G4 * D];     // fp32 combined W_ih @ W_rel[r]
__device__ __nv_bfloat16  g_Wc_hi[(size_t)R_REL * G4 * D];
__device__ __nv_bfloat16  g_Wc_lo[(size_t)R_REL * G4 * D];
__device__ __nv_bfloat16  g_Whh_hi[(size_t)G4 * D];
__device__ __nv_bfloat16  g_Whh_lo[(size_t)G4 * D];
__device__ __nv_bfloat16  g_emb_hi[(size_t)NODES_MAX * D];
__device__ __nv_bfloat16  g_emb_lo[(size_t)NODES_MAX * D];
__device__ float          g_bc[R_REL * G4];
__device__ float          g_gatesx[(size_t)NTOK_MAX * G4];  // per-token input gates (fp32)
__device__ __nv_bfloat16  g_h_hi[2][B_MAX * D];             // ping-pong hidden, split
__device__ __nv_bfloat16  g_h_lo[2][B_MAX * D];
__device__ float          g_cbuf[B_MAX * D];
__device__ int   g_cnt[R_REL];
__device__ int   g_off[R_REL];
__device__ int   g_cur[R_REL];
__device__ int   g_sorted[NTOK_MAX];
__device__ int   g_tokof[T_MAX * B_MAX];

// ---------------- helpers ----------------
__device__ __forceinline__ void mma_bf16(float* c, const unsigned* a, const unsigned* b) {
    asm volatile(
        "mma.sync.aligned.m16n8k16.row.col.f32.bf16.bf16.f32 "
        "{%0,%1,%2,%3}, {%4,%5,%6,%7}, {%8,%9}, {%0,%1,%2,%3};\n"
        : "+f"(c[0]), "+f"(c[1]), "+f"(c[2]), "+f"(c[3])
        : "r"(a[0]), "r"(a[1]), "r"(a[2]), "r"(a[3]), "r"(b[0]), "r"(b[1]));
}

// ---------------- init ----------------
__global__ void init_kernel() {
    int i = blockIdx.x * blockDim.x + threadIdx.x;     // grid covers 524288
    if (i < B_MAX * D) g_cbuf[i] = 0.f;
    if (i < (B_MAX * D) / 2) {                          // zero bf16 buffers as u32
        ((unsigned*)g_h_hi)[i] = 0u;  ((unsigned*)g_h_hi)[i + (B_MAX*D)/2] = 0u;
        ((unsigned*)g_h_lo)[i] = 0u;  ((unsigned*)g_h_lo)[i + (B_MAX*D)/2] = 0u;
    }
    if (i < T_MAX * B_MAX) g_tokof[i] = -1;
    if (i < R_REL) { g_cnt[i] = 0; g_cur[i] = 0; }
}

// ---------------- bucket sort by relation ----------------
__global__ void hist_kernel(const int* __restrict__ rels, int n) {
    int i = blockIdx.x * blockDim.x + threadIdx.x;
    if (i < n) atomicAdd(&g_cnt[rels[i]], 1);
}
__global__ void scan_kernel() {
    int s = 0;
    for (int r = 0; r < R_REL; r++) { g_off[r] = s; g_cur[r] = s; s += g_cnt[r]; }
}
__global__ void scatter_kernel(const int* __restrict__ rels, int n) {
    int i = blockIdx.x * blockDim.x + threadIdx.x;
    if (i < n) { int pos = atomicAdd(&g_cur[rels[i]], 1); g_sorted[pos] = i; }
}
__global__ void tokscatter_kernel(const int* __restrict__ time_idx,
                                  const int* __restrict__ batch_idx, int n) {
    int i = blockIdx.x * blockDim.x + threadIdx.x;
    if (i < n) g_tokof[time_idx[i] * B_MAX + batch_idx[i]] = i;
}

// ---------------- Wc[r] = W_ih @ W_rel[r]  (SIMT fp32, 8.6 GF) ----------------
__global__ __launch_bounds__(256) void combine_wc(const float* __restrict__ Wih,
                                                  const float* __restrict__ Wrel) {
    int r = blockIdx.z;
    int j0 = blockIdx.y * 64, d0 = blockIdx.x * 64;
    __shared__ float As[16][64], Bs[16][64];
    int tid = threadIdx.x, tx = tid & 15, ty = tid >> 4;
    int am = tid >> 2, ak = (tid & 3) << 2;
    int bk = tid >> 4, bd = (tid & 15) << 2;
    const float* B = Wrel + (size_t)r * D * D;
    float acc[4][4] = {};
    for (int k0 = 0; k0 < D; k0 += 16) {
        float4 av = *(const float4*)(Wih + (size_t)(j0 + am) * D + k0 + ak);
        As[ak + 0][am] = av.x; As[ak + 1][am] = av.y; As[ak + 2][am] = av.z; As[ak + 3][am] = av.w;
        *(float4*)&Bs[bk][bd] = *(const float4*)(B + (size_t)(k0 + bk) * D + d0 + bd);
        __syncthreads();
#pragma unroll
        for (int k = 0; k < 16; k++) {
            float4 a = *(const float4*)&As[k][ty << 2];
            float4 b = *(const float4*)&Bs[k][tx << 2];
            float aa[4] = {a.x, a.y, a.z, a.w}, bb[4] = {b.x, b.y, b.z, b.w};
#pragma unroll
            for (int i = 0; i < 4; i++)
#pragma unroll
                for (int j = 0; j < 4; j++) acc[i][j] += aa[i] * bb[j];
        }
        __syncthreads();
    }
#pragma unroll
    for (int i = 0; i < 4; i++)
#pragma unroll
        for (int j = 0; j < 4; j++)
            g_Wc[((size_t)r * G4 + j0 + (ty << 2) + i) * D + d0 + (tx << 2) + j] = acc[i][j];
}

// ---------------- bc[r][j] = W_ih[j,:]·b_rel[r] + b_ih[j] + b_hh[j] ----------------
__global__ void combine_bias(const float* __restrict__ Wih, const float* __restrict__ brel,
                             const float* __restrict__ bih, const float* __restrict__ bhh) {
    int r = blockIdx.y;
    int wid = threadIdx.x >> 5, lane = threadIdx.x & 31;
    int j = blockIdx.x * 8 + wid;
    float s = 0.f;
    for (int k = lane; k < D; k += 32) s += Wih[(size_t)j * D + k] * brel[r * D + k];
#pragma unroll
    for (int o = 16; o; o >>= 1) s += __shfl_xor_sync(0xffffffffu, s, o);
    if (lane == 0) g_bc[r * G4 + j] = s + bih[j] + bhh[j];
}

// ---------------- fp32 -> bf16 hi/lo split ----------------
__global__ void split_kernel(const float* __restrict__ src, __nv_bfloat16* __restrict__ hi,
                             __nv_bfloat16* __restrict__ lo, size_t n) {
    size_t i = (size_t)blockIdx.x * blockDim.x + threadIdx.x;
    size_t stride = (size_t)gridDim.x * blockDim.x;
    for (; i < n; i += stride) {
        float x = src[i];
        __nv_bfloat16 h = __float2bfloat16(x);
        hi[i] = h;
        lo[i] = __float2bfloat16(x - __bfloat162float(h));
    }
}
__global__ void split_dev_kernel(size_t n) {   // splits g_Wc in place into hi/lo
    size_t i = (size_t)blockIdx.x * blockDim.x + threadIdx.x;
    size_t stride = (size_t)gridDim.x * blockDim.x;
    for (; i < n; i += stride) {
        float x = g_Wc[i];
        __nv_bfloat16 h = __float2bfloat16(x);
        g_Wc_hi[i] = h;
        g_Wc_lo[i] = __float2bfloat16(x - __bfloat162float(h));
    }
}

// ===================== shared 64x64xK bf16-split MMA body =====================
// Block: 256 threads = 8 warps, warp w -> (wm = (w&1)*32 rows, wn = (w>>1)*16 cols).
// K-chunk = 32, smem tiles strided at 34 bf16 (17 u32). Register-prefetch pipeline.
#define KCH    32
#define SW     17         // u32 stride per row in smem tiles
#define NCHUNK (D / KCH)  // 16

struct Prefetch { uint4 ah, al, bh, bl; };

__device__ __forceinline__ void gemm_mainloop(
    const unsigned* aHi, const unsigned* aLo,      // thread-private global srcs (advance 16/chunk)
    const unsigned* bHi, const unsigned* bLo,
    unsigned* sAh, unsigned* sAl, unsigned* sBh, unsigned* sBl,
    float acc[2][2][4])
{
    int tid = threadIdx.x;
    int r  = tid >> 2;            // 0..63 : tile row (A) / tile col (B)
    int c4 = (tid & 3) * 4;       // u32 column within chunk
    int lane = tid & 31, wid = tid >> 5;
    int g = lane >> 2, tig = lane & 3;
    int wm = (wid & 1) * 32, wn = (wid >> 1) * 16;

    Prefetch pf;
    pf.ah = *(const uint4*)(aHi); pf.al = *(const uint4*)(aLo);
    pf.bh = *(const uint4*)(bHi); pf.bl = *(const uint4*)(bLo);

    unsigned sbase = (unsigned)(r * SW + c4);

#pragma unroll 1
    for (int ch = 0; ch < NCHUNK; ch++) {
        __syncthreads();   // smem free (previous chunk's readers done)
        *(uint4*)0; // (no-op placeholder removed by compiler)  
        { unsigned* p = sAh + sbase; p[0]=pf.ah.x; p[1]=pf.ah.y; p[2]=pf.ah.z; p[3]=pf.ah.w; }
        { unsigned* p = sAl + sbase; p[0]=pf.al.x; p[1]=pf.al.y; p[2]=pf.al.z; p[3]=pf.al.w; }
        { unsigned* p = sBh + sbase; p[0]=pf.bh.x; p[1]=pf.bh.y; p[2]=pf.bh.z; p[3]=pf.bh.w; }
        { unsigned* p = sBl + sbase; p[0]=pf.bl.x; p[1]=pf.bl.y; p[2]=pf.bl.z; p[3]=pf.bl.w; }
        __syncthreads();
        if (ch + 1 < NCHUNK) {    // issue next chunk's global loads early
            int adv = (ch + 1) * (KCH / 2);
            pf.ah = *(const uint4*)(aHi + adv); pf.al = *(const uint4*)(aLo + adv);
            pf.bh = *(const uint4*)(bHi + adv); pf.bl = *(const uint4*)(bLo + adv);
        }
#pragma unroll
        for (int s = 0; s < 2; s++) {
            unsigned ahf[2][4], alf[2][4], bhf[2][2], blf[2][2];
#pragma unroll
            for (int mt = 0; mt < 2; mt++) {
                int row = wm + mt * 16 + g;
                ahf[mt][0] = sAh[row * SW + s * 8 + tig];
                ahf[mt][1] = sAh[(row + 8) * SW + s * 8 + tig];
                ahf[mt][2] = sAh[row * SW + s * 8 + tig + 4];
                ahf[mt][3] = sAh[(row + 8) * SW + s * 8 + tig + 4];
                alf[mt][0] = sAl[row * SW + s * 8 + tig];
                alf[mt][1] = sAl[(row + 8) * SW + s * 8 + tig];
                alf[mt][2] = sAl[row * SW + s * 8 + tig + 4];
                alf[mt][3] = sAl[(row + 8) * SW + s * 8 + tig + 4];
            }
#pragma unroll
            for (int nt = 0; nt < 2; nt++) {
                int col = wn + nt * 8 + g;
                bhf[nt][0] = sBh[col * SW + s * 8 + tig];
                bhf[nt][1] = sBh[col * SW + s * 8 + tig + 4];
                blf[nt][0] = sBl[col * SW + s * 8 + tig];
                blf[nt][1] = sBl[col * SW + s * 8 + tig + 4];
            }
#pragma unroll
            for (int mt = 0; mt < 2; mt++)
#pragma unroll
                for (int nt = 0; nt < 2; nt++) {
                    mma_bf16(acc[mt][nt], ahf[mt], bhf[nt]);
                    mma_bf16(acc[mt][nt], ahf[mt], blf[nt]);
                    mma_bf16(acc[mt][nt], alf[mt], bhf[nt]);
                }
        }
    }
}

// ---------------- grouped x-projection (tensor): gates_x = embed[node] @ Wc[rel]^T + bc ----------------
__global__ __launch_bounds__(256) void xproj_mma(const int* __restrict__ nodes) {
    __shared__ unsigned sAh[64 * SW], sAl[64 * SW], sBh[64 * SW], sBl[64 * SW];
    __shared__ int s_tok[64], s_node[64];

    int ft = blockIdx.y;
    int rel = -1, tile = 0, cnt = 0, off = 0;
#pragma unroll
    for (int r = 0; r < R_REL; r++) {
        int c = g_cnt[r]; int tr = (c + 63) >> 6;
        if (rel < 0) { if (ft < tr) { rel = r; tile = ft; cnt = c; off = g_off[r]; } else ft -= tr; }
    }
    if (rel < 0) return;
    int j0 = blockIdx.x * 64;
    int tid = threadIdx.x;
    if (tid < 64) {
        int sp = tile * 64 + tid;
        int tok = -1, nd = 0;
        if (sp < cnt) { tok = g_sorted[off + sp]; nd = nodes[tok]; }
        s_tok[tid] = tok; s_node[tid] = nd;
    }
    __syncthreads();

    int r = tid >> 2, c4 = (tid & 3) * 4;
    const unsigned* aHi = (const unsigned*)g_emb_hi + (size_t)s_node[r] * (D / 2) + c4;
    const unsigned* aLo = (const unsigned*)g_emb_lo + (size_t)s_node[r] * (D / 2) + c4;
    size_t brow = (size_t)rel * G4 + j0 + r;
    const unsigned* bHi = (const unsigned*)g_Wc_hi + brow * (D / 2) + c4;
    const unsigned* bLo = (const unsigned*)g_Wc_lo + brow * (D / 2) + c4;

    float acc[2][2][4] = {};
    gemm_mainloop(aHi, aLo, bHi, bLo, sAh, sAl, sBh, sBl, acc);

    int lane = tid & 31, wid = tid >> 5;
    int g = lane >> 2, tig = lane & 3;
    int wm = (wid & 1) * 32, wn = (wid >> 1) * 16;
#pragma unroll
    for (int mt = 0; mt < 2; mt++)
#pragma unroll
        for (int nt = 0; nt < 2; nt++) {
            int rowl = wm + mt * 16 + g;
            int col = j0 + wn + nt * 8 + 2 * tig;
            float2 bb = *(const float2*)(g_bc + rel * G4 + col);
            int tokA = s_tok[rowl];
            if (tokA >= 0) {
                float2 v = { acc[mt][nt][0] + bb.x, acc[mt][nt][1] + bb.y };
                *(float2*)(g_gatesx + (size_t)tokA * G4 + col) = v;
            }
            int tokB = s_tok[rowl + 8];
            if (tokB >= 0) {
                float2 v = { acc[mt][nt][2] + bb.x, acc[mt][nt][3] + bb.y };
                *(float2*)(g_gatesx + (size_t)tokB * G4 + col) = v;
            }
        }
}

// ---------------- one LSTM step (tensor): gates = gates_x + h @ W_hh^T, then cell ----------------
__global__ __launch_bounds__(256) void lstm_step_mma(int t, const int* __restrict__ bsz,
                                                     float* __restrict__ out) {
    __shared__ unsigned sAh[64 * SW], sAl[64 * SW], sBh[64 * SW], sBl[64 * SW];
    __shared__ float gt[64 * 66];

    int bs = bsz[t];
    int row0 = blockIdx.y * 64;
    if (row0 >= bs) return;
    int d0 = blockIdx.x * 16;
    int cur = t & 1, nxt = cur ^ 1;

    int tid = threadIdx.x;
    int r = tid >> 2, c4 = (tid & 3) * 4;
    const unsigned* aHi = (const unsigned*)g_h_hi[cur] + (size_t)(row0 + r) * (D / 2) + c4;
    const unsigned* aLo = (const unsigned*)g_h_lo[cur] + (size_t)(row0 + r) * (D / 2) + c4;
    int whhrow = ((r >> 4) * D) + d0 + (r & 15);       // col jj -> W_hh row
    const unsigned* bHi = (const unsigned*)g_Whh_hi + (size_t)whhrow * (D / 2) + c4;
    const unsigned* bLo = (const unsigned*)g_Whh_lo + (size_t)whhrow * (D / 2) + c4;

    float acc[2][2][4] = {};
    gemm_mainloop(aHi, aLo, bHi, bLo, sAh, sAl, sBh, sBl, acc);

    int lane = tid & 31, wid = tid >> 5;
    int g = lane >> 2, tig = lane & 3;
    int wm = (wid & 1) * 32, wn = (wid >> 1) * 16;
#pragma unroll
    for (int mt = 0; mt < 2; mt++)
#pragma unroll
        for (int nt = 0; nt < 2; nt++) {
            int rowl = wm + mt * 16 + g;
            int cl = wn + nt * 8 + 2 * tig;
            *(float2*)&gt[rowl * 66 + cl]     = make_float2(acc[mt][nt][0], acc[mt][nt][1]);
            *(float2*)&gt[(rowl + 8) * 66 + cl] = make_float2(acc[mt][nt][2], acc[mt][nt][3]);
        }
    __syncthreads();

    __nv_bfloat16* hnh = g_h_hi[nxt];
    __nv_bfloat16* hnl = g_h_lo[nxt];
#pragma unroll
    for (int e = 0; e < 4; e++) {
        int cell = tid + e * 256;
        int row = cell >> 4, dl = cell & 15;
        int grow = row0 + row;
        if (grow < bs) {
            int gd = d0 + dl;
            int tok = g_tokof[t * B_MAX + grow];
            if (tok >= 0) {
                size_t gxb = (size_t)tok * G4 + gd;
                float gi = gt[row * 66 + dl]      + g_gatesx[gxb];
                float gf = gt[row * 66 + 16 + dl] + g_gatesx[gxb + 512];
                float gg = gt[row * 66 + 32 + dl] + g_gatesx[gxb + 1024];
                float go = gt[row * 66 + 48 + dl] + g_gatesx[gxb + 1536];
                float co = g_cbuf[(size_t)grow * D + gd];
                float si = 1.f / (1.f + __expf(-gi));
                float sf = 1.f / (1.f + __expf(-gf));
                float so = 1.f / (1.f + __expf(-go));
                float cn = sf * co + si * tanhf(gg);
                float hv = so * tanhf(cn);
                g_cbuf[(size_t)grow * D + gd] = cn;
                __nv_bfloat16 hh = __float2bfloat16(hv);
                hnh[(size_t)grow * D + gd] = hh;
                hnl[(size_t)grow * D + gd] = __float2bfloat16(hv - __bfloat162float(hh));
                out[(size_t)tok * D + gd] = hv;
            }
        }
    }
}

// ---------------- launch ----------------
extern "C" void kernel_launch(void* const* d_in, const int* in_sizes, int n_in,
                              void* d_out, int out_size) {
    const float* embed     = (const float*)d_in[0];
    const float* Wrel      = (const float*)d_in[1];
    const float* brel      = (const float*)d_in[2];
    const float* Wih       = (const float*)d_in[3];
    const float* Whh       = (const float*)d_in[4];
    const float* bih       = (const float*)d_in[5];
    const float* bhh       = (const float*)d_in[6];
    const int*   nodes     = (const int*)d_in[7];
    const int*   rels      = (const int*)d_in[8];
    const int*   time_idx  = (const int*)d_in[9];
    const int*   batch_idx = (const int*)d_in[10];
    const int*   bsz       = (const int*)d_in[11];
    float* out = (float*)d_out;

    int ntok = in_sizes[7];
    int T    = in_sizes[11];
    if (ntok > NTOK_MAX) ntok = NTOK_MAX;
    if (T > T_MAX) T = T_MAX;

    // static pointers to device globals for split kernels
    __nv_bfloat16 *ehi, *elo, *whi, *wlo;
    cudaGetSymbolAddress((void**)&ehi, g_emb_hi);
    cudaGetSymbolAddress((void**)&elo, g_emb_lo);
    cudaGetSymbolAddress((void**)&whi, g_Whh_hi);
    cudaGetSymbolAddress((void**)&wlo, g_Whh_lo);

    init_kernel<<<(B_MAX * D + 255) / 256, 256>>>();
    combine_wc<<<dim3(D / 64, G4 / 64, R_REL), 256>>>(Wih, Wrel);
    combine_bias<<<dim3(G4 / 8, R_REL), 256>>>(Wih, brel, bih, bhh);
    hist_kernel<<<(ntok + 255) / 256, 256>>>(rels, ntok);
    scan_kernel<<<1, 1>>>();
    scatter_kernel<<<(ntok + 255) / 256, 256>>>(rels, ntok);
    tokscatter_kernel<<<(ntok + 255) / 256, 256>>>(time_idx, batch_idx, ntok);

    size_t n_emb = (size_t)in_sizes[0];
    split_kernel<<<1024, 256>>>(embed, ehi, elo, n_emb);
    split_kernel<<<256, 256>>>(Whh, whi, wlo, (size_t)G4 * D);
    split_dev_kernel<<<2048, 256>>>((size_t)R_REL * G4 * D);

    xproj_mma<<<dim3(G4 / 64, (ntok + 63) / 64 + R_REL), 256>>>(nodes);
    for (int t = 0; t < T; t++)
        lstm_step_mma<<<dim3(D / 16, B_MAX / 64), 256>>>(t, bsz, out);
}

// round 5
// speedup vs baseline: 2.2382x; 1.3832x over previous
#include <cuda_runtime.h>
#include <cuda_bf16.h>
#include <math.h>

#define D        512
#define DU       256          // u32 per D row
#define G4       2048
#define R_REL    8
#define T_MAX    128
#define B_MAX    1024
#define NTOK_MAX 66048
#define NODES_MAX 50000

// ---------------- device scratch ----------------
__device__ __nv_bfloat16 g_emb_hi[(size_t)NODES_MAX * D], g_emb_lo[(size_t)NODES_MAX * D];
__device__ __nv_bfloat16 g_wrel_hi[(size_t)R_REL * D * D], g_wrel_lo[(size_t)R_REL * D * D];
__device__ __nv_bfloat16 g_wih_hi[(size_t)G4 * D], g_wih_lo[(size_t)G4 * D];
__device__ __nv_bfloat16 g_whh_hi[(size_t)G4 * D], g_whh_lo[(size_t)G4 * D];
__device__ unsigned      g_y_hi[(size_t)NTOK_MAX * DU], g_y_lo[(size_t)NTOK_MAX * DU];
__device__ float         g_gatesx[(size_t)NTOK_MAX * G4];
__device__ unsigned      g_h_hi[2][B_MAX * DU], g_h_lo[2][B_MAX * DU];
__device__ float         g_cbuf[B_MAX * D];
__device__ int g_cnt[R_REL], g_off[R_REL], g_cur[R_REL];
__device__ int g_sorted[NTOK_MAX], g_tokof[T_MAX * B_MAX];

// ---------------- ptx helpers ----------------
__device__ __forceinline__ void mma_bf16(float* c, const unsigned* a, const unsigned* b) {
    asm volatile(
        "mma.sync.aligned.m16n8k16.row.col.f32.bf16.bf16.f32 "
        "{%0,%1,%2,%3}, {%4,%5,%6,%7}, {%8,%9}, {%0,%1,%2,%3};\n"
        : "+f"(c[0]), "+f"(c[1]), "+f"(c[2]), "+f"(c[3])
        : "r"(a[0]), "r"(a[1]), "r"(a[2]), "r"(a[3]), "r"(b[0]), "r"(b[1]));
}
__device__ __forceinline__ void ldsm4(unsigned& r0, unsigned& r1, unsigned& r2, unsigned& r3,
                                      unsigned saddr) {
    asm volatile("ldmatrix.sync.aligned.m8n8.x4.shared.b16 {%0,%1,%2,%3}, [%4];"
                 : "=r"(r0), "=r"(r1), "=r"(r2), "=r"(r3) : "r"(saddr));
}
__device__ __forceinline__ void cp16(unsigned sdst, const void* gsrc) {
    asm volatile("cp.async.cg.shared.global [%0], [%1], 16;" :: "r"(sdst), "l"(gsrc));
}
__device__ __forceinline__ void cp_commit() { asm volatile("cp.async.commit_group;"); }
__device__ __forceinline__ void cp_wait1() { asm volatile("cp.async.wait_group 1;"); }
__device__ __forceinline__ void cp_wait0() { asm volatile("cp.async.wait_group 0;"); }

__device__ __forceinline__ void pack2(float v0, float v1, unsigned& hi, unsigned& lo) {
    __nv_bfloat16 h0 = __float2bfloat16(v0), h1 = __float2bfloat16(v1);
    __nv_bfloat16 l0 = __float2bfloat16(v0 - __bfloat162float(h0));
    __nv_bfloat16 l1 = __float2bfloat16(v1 - __bfloat162float(h1));
    hi = (unsigned)__bfloat16_as_ushort(h0) | ((unsigned)__bfloat16_as_ushort(h1) << 16);
    lo = (unsigned)__bfloat16_as_ushort(l0) | ((unsigned)__bfloat16_as_ushort(l1) << 16);
}

// ---------------- small kernels ----------------
__global__ void init_kernel() {
    int i = blockIdx.x * blockDim.x + threadIdx.x;    // grid covers 524288
    if (i < B_MAX * DU) {
        g_h_hi[0][i] = 0u; g_h_hi[1][i] = 0u;
        g_h_lo[0][i] = 0u; g_h_lo[1][i] = 0u;
    }
    if (i < B_MAX * D) g_cbuf[i] = 0.f;
    if (i < T_MAX * B_MAX) g_tokof[i] = -1;
    if (i < R_REL) { g_cnt[i] = 0; g_cur[i] = 0; }
}
__global__ void hist_kernel(const int* __restrict__ rels, int n) {
    int i = blockIdx.x * blockDim.x + threadIdx.x;
    if (i < n) atomicAdd(&g_cnt[rels[i]], 1);
}
__global__ void scan_kernel() {
    int s = 0;
    for (int r = 0; r < R_REL; r++) { g_off[r] = s; g_cur[r] = s; s += g_cnt[r]; }
}
__global__ void scatter_kernel(const int* __restrict__ rels, int n) {
    int i = blockIdx.x * blockDim.x + threadIdx.x;
    if (i < n) { int pos = atomicAdd(&g_cur[rels[i]], 1); g_sorted[pos] = i; }
}
__global__ void tokscatter_kernel(const int* __restrict__ time_idx,
                                  const int* __restrict__ batch_idx, int n) {
    int i = blockIdx.x * blockDim.x + threadIdx.x;
    if (i < n) g_tokof[time_idx[i] * B_MAX + batch_idx[i]] = i;
}
__global__ void split_kernel(const float* __restrict__ src, __nv_bfloat16* __restrict__ hi,
                             __nv_bfloat16* __restrict__ lo, size_t n) {
    size_t i = (size_t)blockIdx.x * blockDim.x + threadIdx.x;
    size_t stride = (size_t)gridDim.x * blockDim.x;
    for (; i < n; i += stride) {
        float x = src[i];
        __nv_bfloat16 h = __float2bfloat16(x);
        hi[i] = h;
        lo[i] = __float2bfloat16(x - __bfloat162float(h));
    }
}

// ================= 64x128xK=512 bf16-split MMA mainloop =================
// smem buffer layout (per buf, u32): Ah[64*20] Al[64*20] Bh[128*20] Bl[128*20]
// two bufs = 15360 u32 = 61440 B. Pitch 20 u32: LDSM conflict-free, cp.async 16B-aligned.
#define AB_   5120u     // bytes of one A half-tile
#define BB_   10240u    // bytes of one B half-tile
#define BUFB_ 30720u    // bytes per buffer
#define GEMM_SMEM 61440
#define STEP_SMEM (61440 + 64 * 132 * 4)

struct GP { const unsigned *ah, *al, *bh0, *bh1, *bl0, *bl1; };

__device__ __forceinline__ void gemm_main(unsigned sm, GP p, float acc[2][4][4]) {
    const int tid = threadIdx.x, lane = tid & 31, wid = tid >> 5;
    const int rA = tid >> 2, c4 = (tid & 3) << 2;
    unsigned st = (unsigned)((rA * 20 + c4) << 2);
    unsigned dAh = sm + st, dAl = dAh + AB_;
    unsigned dBh0 = sm + 2 * AB_ + st, dBh1 = dBh0 + 5120u;
    unsigned dBl0 = dBh0 + BB_, dBl1 = dBl0 + 5120u;
    const int lrow = lane & 15, lk = (lane >> 4) << 2;
    const int wm = (wid & 1) << 5, wn = (wid >> 1) << 5;
    unsigned aA0 = sm + (((wm + lrow) * 20 + lk) << 2);
    unsigned aA1 = sm + (((wm + 16 + lrow) * 20 + lk) << 2);
    unsigned aB0 = sm + 2 * AB_ + (((wn + lrow) * 20 + lk) << 2);
    unsigned aB1 = sm + 2 * AB_ + (((wn + 16 + lrow) * 20 + lk) << 2);

    cp16(dAh, p.ah); cp16(dAl, p.al);
    cp16(dBh0, p.bh0); cp16(dBh1, p.bh1);
    cp16(dBl0, p.bl0); cp16(dBl1, p.bl1);
    cp_commit();

#pragma unroll 1
    for (int ch = 0; ch < 16; ch++) {
        if (ch < 15) {
            unsigned off = ((ch + 1) & 1) * BUFB_;
            int adv = (ch + 1) << 4;
            cp16(dAh + off, p.ah + adv); cp16(dAl + off, p.al + adv);
            cp16(dBh0 + off, p.bh0 + adv); cp16(dBh1 + off, p.bh1 + adv);
            cp16(dBl0 + off, p.bl0 + adv); cp16(dBl1 + off, p.bl1 + adv);
            cp_commit();
            cp_wait1();
        } else cp_wait0();
        __syncthreads();
        unsigned bo = (unsigned)(ch & 1) * BUFB_;
#pragma unroll
        for (int s = 0; s < 2; s++) {
            unsigned so = bo + (unsigned)(s * 32);
            unsigned ah[2][4], al[2][4], bh[4][2], bl[4][2];
            ldsm4(ah[0][0], ah[0][1], ah[0][2], ah[0][3], aA0 + so);
            ldsm4(ah[1][0], ah[1][1], ah[1][2], ah[1][3], aA1 + so);
            ldsm4(al[0][0], al[0][1], al[0][2], al[0][3], aA0 + AB_ + so);
            ldsm4(al[1][0], al[1][1], al[1][2], al[1][3], aA1 + AB_ + so);
            { unsigned r0, r1, r2, r3; ldsm4(r0, r1, r2, r3, aB0 + so);
              bh[0][0] = r0; bh[1][0] = r1; bh[0][1] = r2; bh[1][1] = r3; }
            { unsigned r0, r1, r2, r3; ldsm4(r0, r1, r2, r3, aB1 + so);
              bh[2][0] = r0; bh[3][0] = r1; bh[2][1] = r2; bh[3][1] = r3; }
            { unsigned r0, r1, r2, r3; ldsm4(r0, r1, r2, r3, aB0 + BB_ + so);
              bl[0][0] = r0; bl[1][0] = r1; bl[0][1] = r2; bl[1][1] = r3; }
            { unsigned r0, r1, r2, r3; ldsm4(r0, r1, r2, r3, aB1 + BB_ + so);
              bl[2][0] = r0; bl[3][0] = r1; bl[2][1] = r2; bl[3][1] = r3; }
#pragma unroll
            for (int mt = 0; mt < 2; mt++)
#pragma unroll
                for (int nt = 0; nt < 4; nt++) {
                    mma_bf16(acc[mt][nt], ah[mt], bh[nt]);
                    mma_bf16(acc[mt][nt], ah[mt], bl[nt]);
                    mma_bf16(acc[mt][nt], al[mt], bh[nt]);
                }
        }
        __syncthreads();
    }
}

// ---------------- stage1: y[tok] = embed[node] @ Wrel[rel]^T + b_rel[rel]  (grouped) ----------------
__global__ __launch_bounds__(256) void stage1_mma(const int* __restrict__ nodes,
                                                  const float* __restrict__ brel) {
    extern __shared__ unsigned dyn[];
    unsigned sm = (unsigned)__cvta_generic_to_shared(dyn);
    __shared__ int s_tok[64];
    __shared__ unsigned s_aoff[64];

    int ft = blockIdx.y;
    int rel = -1, tile = 0, cnt = 0, off = 0;
#pragma unroll
    for (int r = 0; r < R_REL; r++) {
        int c = g_cnt[r]; int tr = (c + 63) >> 6;
        if (rel < 0) { if (ft < tr) { rel = r; tile = ft; cnt = c; off = g_off[r]; } else ft -= tr; }
    }
    if (rel < 0) return;
    int n0 = blockIdx.x * 128;
    int tid = threadIdx.x;
    if (tid < 64) {
        int sp = tile * 64 + tid;
        int tok = -1, nd = 0;
        if (sp < cnt) { tok = g_sorted[off + sp]; nd = nodes[tok]; }
        s_tok[tid] = tok; s_aoff[tid] = (unsigned)nd * DU;
    }
    __syncthreads();

    int rA = tid >> 2, c4 = (tid & 3) << 2;
    GP p;
    p.ah = (const unsigned*)g_emb_hi + s_aoff[rA] + c4;
    p.al = (const unsigned*)g_emb_lo + s_aoff[rA] + c4;
    unsigned b0off = (unsigned)(rel * D + n0 + rA) * DU + c4;
    unsigned b1off = (unsigned)(rel * D + n0 + 64 + rA) * DU + c4;
    p.bh0 = (const unsigned*)g_wrel_hi + b0off;
    p.bh1 = (const unsigned*)g_wrel_hi + b1off;
    p.bl0 = (const unsigned*)g_wrel_lo + b0off;
    p.bl1 = (const unsigned*)g_wrel_lo + b1off;

    float acc[2][4][4] = {};
    gemm_main(sm, p, acc);

    int lane = tid & 31, wid = tid >> 5, g = lane >> 2, tig = lane & 3;
    int wm = (wid & 1) << 5, wn = (wid >> 1) << 5;
#pragma unroll
    for (int mt = 0; mt < 2; mt++)
#pragma unroll
        for (int nt = 0; nt < 4; nt++) {
            int rowl = wm + mt * 16 + g;
            int col = n0 + wn + nt * 8 + 2 * tig;
            float b0v = brel[rel * D + col], b1v = brel[rel * D + col + 1];
            int tA = s_tok[rowl];
            if (tA >= 0) {
                unsigned h, l;
                pack2(acc[mt][nt][0] + b0v, acc[mt][nt][1] + b1v, h, l);
                g_y_hi[(size_t)tA * DU + (col >> 1)] = h;
                g_y_lo[(size_t)tA * DU + (col >> 1)] = l;
            }
            int tB = s_tok[rowl + 8];
            if (tB >= 0) {
                unsigned h, l;
                pack2(acc[mt][nt][2] + b0v, acc[mt][nt][3] + b1v, h, l);
                g_y_hi[(size_t)tB * DU + (col >> 1)] = h;
                g_y_lo[(size_t)tB * DU + (col >> 1)] = l;
            }
        }
}

// ---------------- stage2: gates_x[tok] = y[tok] @ Wih^T + b_ih + b_hh ----------------
__global__ __launch_bounds__(256) void stage2_mma(const float* __restrict__ bih,
                                                  const float* __restrict__ bhh, int ntok) {
    extern __shared__ unsigned dyn[];
    unsigned sm = (unsigned)__cvta_generic_to_shared(dyn);
    int row0 = blockIdx.y * 64, j0 = blockIdx.x * 128;
    int tid = threadIdx.x;
    int rA = tid >> 2, c4 = (tid & 3) << 2;
    int ar = row0 + rA; int arc = ar < ntok ? ar : ntok - 1;
    GP p;
    p.ah = g_y_hi + (size_t)arc * DU + c4;
    p.al = g_y_lo + (size_t)arc * DU + c4;
    unsigned b0off = (unsigned)(j0 + rA) * DU + c4;
    unsigned b1off = (unsigned)(j0 + 64 + rA) * DU + c4;
    p.bh0 = (const unsigned*)g_wih_hi + b0off;
    p.bh1 = (const unsigned*)g_wih_hi + b1off;
    p.bl0 = (const unsigned*)g_wih_lo + b0off;
    p.bl1 = (const unsigned*)g_wih_lo + b1off;

    float acc[2][4][4] = {};
    gemm_main(sm, p, acc);

    int lane = tid & 31, wid = tid >> 5, g = lane >> 2, tig = lane & 3;
    int wm = (wid & 1) << 5, wn = (wid >> 1) << 5;
#pragma unroll
    for (int mt = 0; mt < 2; mt++)
#pragma unroll
        for (int nt = 0; nt < 4; nt++) {
            int rowl = wm + mt * 16 + g;
            int col = j0 + wn + nt * 8 + 2 * tig;
            float bb0 = bih[col] + bhh[col], bb1 = bih[col + 1] + bhh[col + 1];
            int tA = row0 + rowl;
            if (tA < ntok) {
                float2 v = { acc[mt][nt][0] + bb0, acc[mt][nt][1] + bb1 };
                *(float2*)&g_gatesx[(size_t)tA * G4 + col] = v;
            }
            int tB = row0 + rowl + 8;
            if (tB < ntok) {
                float2 v = { acc[mt][nt][2] + bb0, acc[mt][nt][3] + bb1 };
                *(float2*)&g_gatesx[(size_t)tB * G4 + col] = v;
            }
        }
}

// ---------------- one LSTM step: gates = gates_x + h @ Whh^T, then cell ----------------
__global__ __launch_bounds__(256) void step_mma(int t, const int* __restrict__ bsz,
                                                float* __restrict__ out) {
    extern __shared__ unsigned dyn[];
    unsigned sm = (unsigned)__cvta_generic_to_shared(dyn);
    int bs = bsz[t];
    int row0 = blockIdx.y * 64;
    if (row0 >= bs) return;
    int d0 = blockIdx.x * 32;
    int cur = t & 1, nxt = cur ^ 1;
    int tid = threadIdx.x;
    int rA = tid >> 2, c4 = (tid & 3) << 2;

    GP p;
    p.ah = g_h_hi[cur] + (unsigned)(row0 + rA) * DU + c4;
    p.al = g_h_lo[cur] + (unsigned)(row0 + rA) * DU + c4;
    // block col c (0..127) -> Whh row (c>>5)*512 + d0 + (c&31)
    unsigned wr0 = (unsigned)(((rA >> 5) * D) + d0 + (rA & 31)) * DU + c4;
    unsigned wr1 = (unsigned)(((2 + (rA >> 5)) * D) + d0 + (rA & 31)) * DU + c4;
    p.bh0 = (const unsigned*)g_whh_hi + wr0;
    p.bh1 = (const unsigned*)g_whh_hi + wr1;
    p.bl0 = (const unsigned*)g_whh_lo + wr0;
    p.bl1 = (const unsigned*)g_whh_lo + wr1;

    float acc[2][4][4] = {};
    gemm_main(sm, p, acc);

    float* gt = (float*)(dyn + 15360);    // after the two gemm buffers
    int lane = tid & 31, wid = tid >> 5, g = lane >> 2, tig = lane & 3;
    int wm = (wid & 1) << 5, wn = (wid >> 1) << 5;
#pragma unroll
    for (int mt = 0; mt < 2; mt++)
#pragma unroll
        for (int nt = 0; nt < 4; nt++) {
            int rowl = wm + mt * 16 + g;
            int cl = wn + nt * 8 + 2 * tig;
            *(float2*)&gt[rowl * 132 + cl] = make_float2(acc[mt][nt][0], acc[mt][nt][1]);
            *(float2*)&gt[(rowl + 8) * 132 + cl] = make_float2(acc[mt][nt][2], acc[mt][nt][3]);
        }
    __syncthreads();

    unsigned* hnh = g_h_hi[nxt];
    unsigned* hnl = g_h_lo[nxt];
#pragma unroll
    for (int e = 0; e < 4; e++) {
        int cp2 = tid + e * 256;           // 1024 d-pairs: 64 rows x 16 pairs
        int row = cp2 >> 4, dp = (cp2 & 15) << 1;
        int grow = row0 + row;
        if (grow < bs) {
            int tok = g_tokof[t * B_MAX + grow];
            if (tok >= 0) {
                int gd = d0 + dp;
                size_t gx = (size_t)tok * G4 + gd;
                float2 xi = *(const float2*)&g_gatesx[gx];
                float2 xf = *(const float2*)&g_gatesx[gx + 512];
                float2 xg = *(const float2*)&g_gatesx[gx + 1024];
                float2 xo = *(const float2*)&g_gatesx[gx + 1536];
                float gi0 = gt[row * 132 + dp]      + xi.x, gi1 = gt[row * 132 + dp + 1]      + xi.y;
                float gf0 = gt[row * 132 + 32 + dp] + xf.x, gf1 = gt[row * 132 + 32 + dp + 1] + xf.y;
                float gg0 = gt[row * 132 + 64 + dp] + xg.x, gg1 = gt[row * 132 + 64 + dp + 1] + xg.y;
                float go0 = gt[row * 132 + 96 + dp] + xo.x, go1 = gt[row * 132 + 96 + dp + 1] + xo.y;
                float2 c2 = *(const float2*)&g_cbuf[(size_t)grow * D + gd];
                float si0 = 1.f / (1.f + __expf(-gi0)), si1 = 1.f / (1.f + __expf(-gi1));
                float sf0 = 1.f / (1.f + __expf(-gf0)), sf1 = 1.f / (1.f + __expf(-gf1));
                float so0 = 1.f / (1.f + __expf(-go0)), so1 = 1.f / (1.f + __expf(-go1));
                float cn0 = sf0 * c2.x + si0 * tanhf(gg0);
                float cn1 = sf1 * c2.y + si1 * tanhf(gg1);
                float hv0 = so0 * tanhf(cn0);
                float hv1 = so1 * tanhf(cn1);
                *(float2*)&g_cbuf[(size_t)grow * D + gd] = make_float2(cn0, cn1);
                *(float2*)&out[(size_t)tok * D + gd] = make_float2(hv0, hv1);
                unsigned hh, hl;
                pack2(hv0, hv1, hh, hl);
                hnh[(size_t)grow * DU + (gd >> 1)] = hh;
                hnl[(size_t)grow * DU + (gd >> 1)] = hl;
            }
        }
    }
}

// ---------------- launch ----------------
extern "C" void kernel_launch(void* const* d_in, const int* in_sizes, int n_in,
                              void* d_out, int out_size) {
    const float* embed     = (const float*)d_in[0];
    const float* Wrel      = (const float*)d_in[1];
    const float* brel      = (const float*)d_in[2];
    const float* Wih       = (const float*)d_in[3];
    const float* Whh       = (const float*)d_in[4];
    const float* bih       = (const float*)d_in[5];
    const float* bhh       = (const float*)d_in[6];
    const int*   nodes     = (const int*)d_in[7];
    const int*   rels      = (const int*)d_in[8];
    const int*   time_idx  = (const int*)d_in[9];
    const int*   batch_idx = (const int*)d_in[10];
    const int*   bsz       = (const int*)d_in[11];
    float* out = (float*)d_out;

    int ntok = in_sizes[7];
    int T    = in_sizes[11];
    if (ntok > NTOK_MAX) ntok = NTOK_MAX;
    if (T > T_MAX) T = T_MAX;

    static int attr_done = 0;
    cudaFuncSetAttribute(stage1_mma, cudaFuncAttributeMaxDynamicSharedMemorySize, GEMM_SMEM);
    cudaFuncSetAttribute(stage2_mma, cudaFuncAttributeMaxDynamicSharedMemorySize, GEMM_SMEM);
    cudaFuncSetAttribute(step_mma,   cudaFuncAttributeMaxDynamicSharedMemorySize, STEP_SMEM);
    (void)attr_done;

    __nv_bfloat16 *ehi, *elo, *rhi, *rlo, *ihi, *ilo, *hhi, *hlo;
    cudaGetSymbolAddress((void**)&ehi, g_emb_hi);
    cudaGetSymbolAddress((void**)&elo, g_emb_lo);
    cudaGetSymbolAddress((void**)&rhi, g_wrel_hi);
    cudaGetSymbolAddress((void**)&rlo, g_wrel_lo);
    cudaGetSymbolAddress((void**)&ihi, g_wih_hi);
    cudaGetSymbolAddress((void**)&ilo, g_wih_lo);
    cudaGetSymbolAddress((void**)&hhi, g_whh_hi);
    cudaGetSymbolAddress((void**)&hlo, g_whh_lo);

    init_kernel<<<(B_MAX * D + 255) / 256, 256>>>();
    hist_kernel<<<(ntok + 255) / 256, 256>>>(rels, ntok);
    scan_kernel<<<1, 1>>>();
    scatter_kernel<<<(ntok + 255) / 256, 256>>>(rels, ntok);
    tokscatter_kernel<<<(ntok + 255) / 256, 256>>>(time_idx, batch_idx, ntok);

    split_kernel<<<1024, 256>>>(embed, ehi, elo, (size_t)in_sizes[0]);
    split_kernel<<<512, 256>>>(Wrel, rhi, rlo, (size_t)R_REL * D * D);
    split_kernel<<<256, 256>>>(Wih, ihi, ilo, (size_t)G4 * D);
    split_kernel<<<256, 256>>>(Whh, hhi, hlo, (size_t)G4 * D);

    int rowtiles = (ntok + 63) / 64;
    stage1_mma<<<dim3(4, rowtiles + R_REL), 256, GEMM_SMEM>>>(nodes, brel);
    stage2_mma<<<dim3(16, rowtiles), 256, GEMM_SMEM>>>(bih, bhh, ntok);
    for (int t = 0; t < T; t++)
        step_mma<<<dim3(16, 16), 256, STEP_SMEM>>>(t, bsz, out);
}